// round 17
// baseline (speedup 1.0000x reference)
#include <cuda_runtime.h>
#include <cuda_fp16.h>
#include <cstdint>

#define DIM     64
#define KC      8192
#define NP      32768
#define MT      256          // points per CTA
#define NT      64           // codes per tile
#define NTILES  (KC / NT)    // 128
#define GT      512
#define SMLD    176          // row stride bytes (11*16, odd -> conflict-free ldsm)
#define ROWW    44           // u32 words per row

// fp16 rows: [x(64) | 1,1,0.. (16)] for A; [c(64) | -nc/2 hi,lo, 0.. (16)] for B
__device__ __align__(16) char d_A16[NP * SMLD];   // 5.8 MB
__device__ __align__(16) char d_B16[KC * SMLD];   // 1.4 MB
__device__ __align__(16) float d_cn[KC];
__device__ int2  d_cand[NP];

// SMEM: A 256x176 | B 2x 64x176 | mbar 2x8
#define S_A    0
#define S_B    45056
#define BUFSZ  11264
#define S_MB   67584
#define SMEM_G 67616

// ---------------------------------------------------------------------------
// helpers (all generic PTX, sm_90)
// ---------------------------------------------------------------------------
__device__ __forceinline__ uint32_t smem_u32(const void* p) {
    uint32_t a;
    asm("{ .reg .u64 t; cvta.to.shared.u64 t, %1; cvt.u32.u64 %0, t; }"
        : "=r"(a) : "l"(p));
    return a;
}
__device__ __forceinline__ void bulkcp(uint32_t dst, const void* src,
                                       uint32_t bytes, uint32_t mbar) {
    asm volatile(
        "cp.async.bulk.shared::cluster.global.mbarrier::complete_tx::bytes "
        "[%0], [%1], %2, [%3];"
        :: "r"(dst), "l"(src), "r"(bytes), "r"(mbar) : "memory");
}
#define MBAR_INIT(a, n) \
    asm volatile("mbarrier.init.shared.b64 [%0], %1;" :: "r"(a), "r"(n) : "memory")
#define MBAR_EXPECT(a, bytes) \
    asm volatile("mbarrier.arrive.expect_tx.shared.b64 _, [%0], %1;" \
                 :: "r"(a), "r"(bytes) : "memory")
__device__ __forceinline__ void mbar_wait(uint32_t mbar, uint32_t parity) {
    asm volatile(
        "{\n\t.reg .pred P;\n\t"
        "WL_%=:\n\t"
        "mbarrier.try_wait.parity.acquire.cta.shared::cta.b64 P, [%0], %1, 0x989680;\n\t"
        "@P bra.uni WD_%=;\n\t"
        "bra.uni WL_%=;\n\t"
        "WD_%=:\n\t}"
        :: "r"(mbar), "r"(parity) : "memory");
}
__device__ __forceinline__ void ldm_x4(uint32_t* r, uint32_t addr) {
    asm volatile("ldmatrix.sync.aligned.m8n8.x4.shared.b16 {%0,%1,%2,%3}, [%4];"
                 : "=r"(r[0]), "=r"(r[1]), "=r"(r[2]), "=r"(r[3]) : "r"(addr));
}
__device__ __forceinline__ void mma_f16(float* d, const uint32_t* a,
                                        uint32_t b0, uint32_t b1) {
    asm volatile(
        "mma.sync.aligned.m16n8k16.row.col.f32.f16.f16.f32 "
        "{%0,%1,%2,%3}, {%4,%5,%6,%7}, {%8,%9}, {%0,%1,%2,%3};"
        : "+f"(d[0]), "+f"(d[1]), "+f"(d[2]), "+f"(d[3])
        : "r"(a[0]), "r"(a[1]), "r"(a[2]), "r"(a[3]), "r"(b0), "r"(b1));
}

// ---------------------------------------------------------------------------
// prep kernels
// ---------------------------------------------------------------------------
__global__ void __launch_bounds__(256) prep_cn(const float* __restrict__ cb) {
    int k = blockIdx.x * 256 + threadIdx.x;
    const float* row = cb + (size_t)k * DIM;
    float s = 0.f;
#pragma unroll
    for (int i = 0; i < DIM; i++)
        s = __fadd_rn(s, __fmul_rn(row[i], row[i]));
    d_cn[k] = s;
}

__device__ __forceinline__ uint32_t pack_h2(float a, float b) {
    __half h0 = __float2half_rn(a);
    __half h1 = __float2half_rn(b);
    return (uint32_t)__half_as_ushort(h0) | ((uint32_t)__half_as_ushort(h1) << 16);
}

// A rows: 64 fp16 x | (1,1) | zeros ; 176B rows, contiguous by point
__global__ void __launch_bounds__(256) prep_A(const float* __restrict__ ze) {
    __shared__ float xs[DIM * 128];
    const int tid = threadIdx.x;
    const int n0  = blockIdx.x * 128;
    const int b   = n0 >> 12;
    const int hw0 = n0 & 4095;
    const float* zb = ze + (size_t)b * DIM * 4096 + hw0;
#pragma unroll
    for (int it = 0; it < 32; it++) {
        int e = tid + it * 256;
        int nl = e & 127, d = e >> 7;
        xs[d * 128 + nl] = zb[(size_t)d * 4096 + nl];
    }
    __syncthreads();
    uint32_t* out = (uint32_t*)d_A16 + (size_t)blockIdx.x * 128 * ROWW;
#pragma unroll
    for (int i = 0; i < 22; i++) {
        int e   = tid + i * 256;      // 0..5631
        int row = e / ROWW;
        int w   = e % ROWW;
        uint32_t u = 0u;
        if (w < 32) {
            int d0 = w * 2;
            u = pack_h2(xs[d0 * 128 + row], xs[(d0 + 1) * 128 + row]);
        } else if (w == 32) {
            u = 0x3C003C00u;          // (1.0h, 1.0h)
        }
        out[row * ROWW + w] = u;
    }
}

// B rows: 64 fp16 c | (-nc/2 hi, lo) | zeros
__global__ void __launch_bounds__(256) prep_B(const float* __restrict__ cb) {
    int idx = blockIdx.x * 256 + threadIdx.x;   // 0 .. KC*ROWW-1
    int row = idx / ROWW;
    int w   = idx % ROWW;
    uint32_t u = 0u;
    if (w < 32) {
        int d0 = w * 2;
        u = pack_h2(cb[(size_t)row * DIM + d0], cb[(size_t)row * DIM + d0 + 1]);
    } else if (w == 32) {
        float v = -0.5f * d_cn[row];
        __half hh = __float2half_rn(v);
        __half hl = __float2half_rn(v - __half2float(hh));
        u = (uint32_t)__half_as_ushort(hh) | ((uint32_t)__half_as_ushort(hl) << 16);
    }
    ((uint32_t*)d_B16)[(size_t)row * ROWW + w] = u;
}

// ---------------------------------------------------------------------------
// GEMM: MT=256, GT=512 (8M x 2N warps, warp tile 32x32), K=80 nc-folded,
// A fragments hoisted to registers (loaded once), pair-max pair-id epilogue.
// ---------------------------------------------------------------------------
__global__ void __launch_bounds__(GT, 1) gemm_kernel() {
    extern __shared__ char smem[];
    const uint32_t sb = smem_u32(smem);
    const int tid = threadIdx.x;
    const int wid = tid >> 5;
    const int l   = tid & 31;
    const int wm  = wid >> 1;         // M-warp 0..7 (32 rows each)
    const int wn  = wid & 1;          // N-warp 0..1 (32 cols each)
    const int m0  = blockIdx.x * MT;

    if (tid == 0) {
        MBAR_INIT(sb + S_MB, 1);
        MBAR_INIT(sb + S_MB + 8, 1);
    }
    __syncthreads();
    if (tid == 0) {
        MBAR_EXPECT(sb + S_MB, 45056u + 11264u);
        bulkcp(sb + S_A, d_A16 + (size_t)blockIdx.x * 45056, 45056u, sb + S_MB);
        bulkcp(sb + S_B, d_B16, 11264u, sb + S_MB);
        MBAR_EXPECT(sb + S_MB + 8, 11264u);
        bulkcp(sb + S_B + BUFSZ, d_B16 + 11264, 11264u, sb + S_MB + 8);
    }

    // ldmatrix base addresses
    const uint32_t aA0 = sb + S_A + (wm * 32 + (l & 15)) * SMLD + (l >> 4) * 16;
    const uint32_t aA1 = aA0 + 16 * SMLD;
    const uint32_t bRow = (uint32_t)(wn * 32 + (l & 7) + ((l >> 3) & 1) * 8);
    const uint32_t aB0 = sb + S_B + bRow * SMLD + (l >> 4) * 16;
    const uint32_t aB1 = aB0 + 16 * SMLD;   // +16 cols of codes

    // Wait for A (+B0), then hoist A fragments: constant across ALL tiles.
    mbar_wait(sb + S_MB, 0);
    uint32_t afr[5][2][4];
#pragma unroll
    for (int ks = 0; ks < 5; ks++) {
        ldm_x4(afr[ks][0], aA0 + ks * 32);
        ldm_x4(afr[ks][1], aA1 + ks * 32);
    }

    const int cb0 = wn * 32 + 2 * (l & 3);   // epilogue column base

    // 4 MAX trackers of pair-maxes: s = mt*2 + half; ids are PAIR ids
    float b1[4], b2[4];
    int   i1[4], i2[4];
#pragma unroll
    for (int s = 0; s < 4; s++) { b1[s] = -3.4e38f; b2[s] = -3.4e38f; i1[s] = 0; i2[s] = 0; }

#pragma unroll 1
    for (int t = 0; t < NTILES; t++) {
        const int buf = t & 1;
        const uint32_t boff = (uint32_t)buf * BUFSZ;
        mbar_wait(sb + S_MB + 8 * buf, (t >> 1) & 1);

        float acc[2][4][4];
#pragma unroll
        for (int mt = 0; mt < 2; mt++)
#pragma unroll
            for (int j = 0; j < 4; j++)
#pragma unroll
                for (int q = 0; q < 4; q++) acc[mt][j][q] = 0.f;

#pragma unroll
        for (int ks = 0; ks < 5; ks++) {
            const uint32_t koff = (uint32_t)(ks * 32);   // 16 fp16 = 32 B
            uint32_t rbA[4], rbB[4];
            ldm_x4(rbA, aB0 + boff + koff);
            ldm_x4(rbB, aB1 + boff + koff);
            mma_f16(acc[0][0], afr[ks][0], rbA[0], rbA[2]);
            mma_f16(acc[0][1], afr[ks][0], rbA[1], rbA[3]);
            mma_f16(acc[0][2], afr[ks][0], rbB[0], rbB[2]);
            mma_f16(acc[0][3], afr[ks][0], rbB[1], rbB[3]);
            mma_f16(acc[1][0], afr[ks][1], rbA[0], rbA[2]);
            mma_f16(acc[1][1], afr[ks][1], rbA[1], rbA[3]);
            mma_f16(acc[1][2], afr[ks][1], rbB[0], rbB[2]);
            mma_f16(acc[1][3], afr[ks][1], rbB[1], rbB[3]);
        }

        __syncthreads();                       // all warps done reading buf
        if (tid == 0 && t + 2 < NTILES) {
            uint32_t mb = sb + S_MB + 8 * buf;
            MBAR_EXPECT(mb, 11264u);
            bulkcp(sb + S_B + boff, d_B16 + (size_t)(t + 2) * 11264, 11264u, mb);
        }

        // epilogue: pair-max tournament, store PAIR ids only
        const int pb = (t * NT + cb0) >> 1;    // pair-id base
#pragma unroll
        for (int j = 0; j < 4; j++) {
            const int pid = pb + j * 4;
#pragma unroll
            for (int mt = 0; mt < 2; mt++) {
                const int s0 = mt * 2;
                const int s1 = mt * 2 + 1;
                float p0 = fmaxf(acc[mt][j][0], acc[mt][j][1]);   // row r
                float p1 = fmaxf(acc[mt][j][2], acc[mt][j][3]);   // row r+8
                if (p0 > b1[s0]) { b2[s0] = b1[s0]; i2[s0] = i1[s0]; b1[s0] = p0; i1[s0] = pid; }
                else if (p0 > b2[s0]) { b2[s0] = p0; i2[s0] = pid; }
                if (p1 > b1[s1]) { b2[s1] = b1[s1]; i2[s1] = i1[s1]; b1[s1] = p1; i1[s1] = pid; }
                else if (p1 > b2[s1]) { b2[s1] = p1; i2[s1] = pid; }
            }
        }
    }

    // quad merge (lanes sharing l>>2 hold same rows)
#pragma unroll
    for (int s = 0; s < 4; s++) {
#pragma unroll
        for (int off = 1; off <= 2; off <<= 1) {
            float t1 = __shfl_xor_sync(0xFFFFFFFFu, b1[s], off);
            int   j1 = __shfl_xor_sync(0xFFFFFFFFu, i1[s], off);
            float t2 = __shfl_xor_sync(0xFFFFFFFFu, b2[s], off);
            int   j2 = __shfl_xor_sync(0xFFFFFFFFu, i2[s], off);
            if (t1 > b1[s]) {
                float nb2 = fmaxf(b1[s], t2);
                int   ni2 = (t2 > b1[s]) ? j2 : i1[s];
                b1[s] = t1; i1[s] = j1; b2[s] = nb2; i2[s] = ni2;
            } else if (t1 > b2[s]) {
                b2[s] = t1; i2[s] = j1;
            }
        }
    }

    // cross-N-warp merge via smem (reuse B region; all reads done)
    float4* red = (float4*)(smem + S_B);       // [256 rows][2 wn]
    if ((l & 3) == 0) {
#pragma unroll
        for (int s = 0; s < 4; s++) {
            int row = wm * 32 + (s >> 1) * 16 + (s & 1) * 8 + (l >> 2);
            red[row * 2 + wn] = make_float4(b1[s], __int_as_float(i1[s]),
                                            b2[s], __int_as_float(i2[s]));
        }
    }
    __syncthreads();
    if (tid < MT) {
        float4 A4 = red[tid * 2 + 0];
        float4 B4 = red[tid * 2 + 1];
        float s1 = A4.x, s2 = A4.z;
        int   k1 = __float_as_int(A4.y), k2 = __float_as_int(A4.w);
        float t1 = B4.x, t2 = B4.z;
        int   j1 = __float_as_int(B4.y), j2 = __float_as_int(B4.w);
        if (t1 > s1) {
            float n2v = fmaxf(s1, t2);
            int   n2x = (t2 > s1) ? j2 : k1;
            s1 = t1; k1 = j1; s2 = n2v; k2 = n2x;
        } else if (t1 > s2) {
            s2 = t1; k2 = j1;
        }
        d_cand[m0 + tid] = make_int2(k1, k2);   // two PAIR ids
    }
}

// ---------------------------------------------------------------------------
// finalize: exact rescore of 4 candidates (2 pairs, reference rounding) + gather
// ---------------------------------------------------------------------------
__global__ void __launch_bounds__(128) finalize(const float* __restrict__ ze,
                                                const float* __restrict__ cb,
                                                float* __restrict__ out) {
    __shared__ int bx[64];
    const int tid = threadIdx.x;
    const int n0  = blockIdx.x * 64;
    const int b   = n0 >> 12;
    const int hw0 = n0 & 4095;

    if (tid < 64) {
        const int n  = n0 + tid;
        const int hw = hw0 + tid;
        float x[DIM];
#pragma unroll
        for (int d = 0; d < DIM; d++)
            x[d] = ze[(size_t)(b * DIM + d) * 4096 + hw];
        float nx = 0.f;
#pragma unroll
        for (int d = 0; d < DIM; d++)
            nx = __fadd_rn(nx, __fmul_rn(x[d], x[d]));
        int2 cd = d_cand[n];
        int pa = min(cd.x, cd.y), pb = max(cd.x, cd.y);
        int cands[4] = {2 * pa, 2 * pa + 1, 2 * pb, 2 * pb + 1};  // ascending
        float bd = 3.4e38f;
        int   bi = 0x7fffffff;
#pragma unroll
        for (int q = 0; q < 4; q++) {
            int k = cands[q];
            const float* r = cb + (size_t)k * DIM;
            float m = 0.f;
#pragma unroll
            for (int d = 0; d < DIM; d++)
                m = __fmaf_rn(x[d], r[d], m);
            float d2 = __fadd_rn(__fadd_rn(nx, -__fmul_rn(2.0f, m)), d_cn[k]);
            if (d2 < bd || (d2 == bd && k < bi)) { bd = d2; bi = k; }
        }
        bx[tid] = bi;
    }
    __syncthreads();

    float* ob = out + (size_t)b * DIM * 4096 + hw0;
#pragma unroll
    for (int it = 0; it < 32; it++) {
        int e = tid + it * 128;
        int nl = e & 63, d = e >> 6;
        ob[(size_t)d * 4096 + nl] = cb[(size_t)bx[nl] * DIM + d];
    }
}

extern "C" void kernel_launch(void* const* d_in, const int* in_sizes, int n_in,
                              void* d_out, int out_size) {
    const float* ze = (const float*)d_in[0];   // [8,64,64,64] f32
    const float* cb = (const float*)d_in[1];   // [8192,64] f32
    float* out = (float*)d_out;

    cudaFuncSetAttribute(gemm_kernel, cudaFuncAttributeMaxDynamicSharedMemorySize,
                         SMEM_G);

    prep_cn<<<KC / 256, 256>>>(cb);
    prep_A<<<NP / 128, 256>>>(ze);
    prep_B<<<(KC * ROWW) / 256, 256>>>(cb);
    gemm_kernel<<<NP / MT, GT, SMEM_G>>>();
    finalize<<<NP / 64, 128>>>(ze, cb, out);
}